// round 4
// baseline (speedup 1.0000x reference)
#include <cuda_runtime.h>
#include <math.h>

// RotationPerturbationLayer: dense [B,N,N] tent matmul == bilinear 4-tap
// gather with zero-fill. Latency-bound tiny kernel: 4 pixels/thread,
// fast-math sincos, float4 stores, 2D grid (no int division on b).

#define RP_H 80
#define RP_W 80
#define RP_C 3
#define RP_B 4
#define RP_N (RP_H * RP_W)

// 64 threads/block, 4 x-adjacent pixels per thread -> 256 px/block
// 1600 pixel-groups per image -> gridDim.x = 25, gridDim.y = B
__global__ void __launch_bounds__(64)
rotation_bilinear_v2(const float* __restrict__ theta,
                     const float* __restrict__ image,
                     float* __restrict__ out)
{
    const int b = blockIdx.y;
    const int p = blockIdx.x * 64 + threadIdx.x;   // pixel-group [0, 1600)
    const int gy  = p / 20;                        // 20 groups per row
    const int gx4 = (p - gy * 20) * 4;             // first x of the group

    const float cx = (RP_W - 1) * 0.5f;
    const float cy = (RP_H - 1) * 0.5f;

    const float th = __ldg(theta + b) * 0.017453292519943295f;
    float s, c;
    __sincosf(th, &s, &c);

    const float yr = (float)gy - cy;
    // base src for gx4, then step by (c, -s) per +1 in x
    const float sx_base = fmaf(c, (float)gx4 - cx, fmaf(s, yr, cx));
    const float sy_base = fmaf(-s, (float)gx4 - cx, fmaf(c, yr, cy));

    float acc0[4], acc1[4], acc2[4];

    #pragma unroll
    for (int j = 0; j < 4; j++) {
        const float sx = fmaf(c, (float)j, sx_base);
        const float sy = fmaf(-s, (float)j, sy_base);

        const int x0 = __float2int_rd(sx);
        const int y0 = __float2int_rd(sy);
        const float fx = sx - (float)x0;
        const float fy = sy - (float)y0;
        const int x1 = x0 + 1;
        const int y1 = y0 + 1;

        const float wx0 = (x0 >= 0 && x0 < RP_W) ? (1.0f - fx) : 0.0f;
        const float wx1 = (x1 >= 0 && x1 < RP_W) ? fx          : 0.0f;
        const float wy0 = (y0 >= 0 && y0 < RP_H) ? (1.0f - fy) : 0.0f;
        const float wy1 = (y1 >= 0 && y1 < RP_H) ? fy          : 0.0f;

        const float w00 = wy0 * wx0;
        const float w01 = wy0 * wx1;
        const float w10 = wy1 * wx0;
        const float w11 = wy1 * wx1;

        const int cx0 = min(max(x0, 0), RP_W - 1);
        const int cx1 = min(max(x1, 0), RP_W - 1);
        const int cy0 = min(max(y0, 0), RP_H - 1);
        const int cy1 = min(max(y1, 0), RP_H - 1);

        const int o00 = cy0 * RP_W + cx0;
        const int o01 = cy0 * RP_W + cx1;
        const int o10 = cy1 * RP_W + cx0;
        const int o11 = cy1 * RP_W + cx1;

        {
            const float* img = image;
            float v = w00 * __ldg(img + o00);
            v = fmaf(w01, __ldg(img + o01), v);
            v = fmaf(w10, __ldg(img + o10), v);
            v = fmaf(w11, __ldg(img + o11), v);
            acc0[j] = v;
        }
        {
            const float* img = image + RP_N;
            float v = w00 * __ldg(img + o00);
            v = fmaf(w01, __ldg(img + o01), v);
            v = fmaf(w10, __ldg(img + o10), v);
            v = fmaf(w11, __ldg(img + o11), v);
            acc1[j] = v;
        }
        {
            const float* img = image + 2 * RP_N;
            float v = w00 * __ldg(img + o00);
            v = fmaf(w01, __ldg(img + o01), v);
            v = fmaf(w10, __ldg(img + o10), v);
            v = fmaf(w11, __ldg(img + o11), v);
            acc2[j] = v;
        }
    }

    const int n = gy * RP_W + gx4;  // 16B-aligned (gx4 % 4 == 0)
    float4* o0 = (float4*)(out + (b * RP_C + 0) * RP_N + n);
    float4* o1 = (float4*)(out + (b * RP_C + 1) * RP_N + n);
    float4* o2 = (float4*)(out + (b * RP_C + 2) * RP_N + n);
    *o0 = make_float4(acc0[0], acc0[1], acc0[2], acc0[3]);
    *o1 = make_float4(acc1[0], acc1[1], acc1[2], acc1[3]);
    *o2 = make_float4(acc2[0], acc2[1], acc2[2], acc2[3]);
}

extern "C" void kernel_launch(void* const* d_in, const int* in_sizes, int n_in,
                              void* d_out, int out_size)
{
    const float* theta = (const float*)d_in[0];  // [4]
    const float* image = (const float*)d_in[1];  // [3,80,80]
    float* out = (float*)d_out;                  // [4,3,80,80]

    dim3 grid(25, RP_B);   // 1600 groups / 64 threads = 25 blocks per image
    rotation_bilinear_v2<<<grid, 64>>>(theta, image, out);
}

// round 5
// speedup vs baseline: 1.3155x; 1.3155x over previous
#include <cuda_runtime.h>
#include <math.h>

// RotationPerturbationLayer: dense [B,N,N] tent matmul == 4-tap bilinear
// gather with zero-fill. Latency-exposure kernel: keep v1's winning shape
// (1 px/thread, 256 thr x 100 blocks, 8 warps/CTA for TLP) and shorten the
// per-warp dependent chain (__sincosf, no division, no guard).

#define RP_H 80
#define RP_W 80
#define RP_C 3
#define RP_B 4
#define RP_N (RP_H * RP_W)

__global__ void __launch_bounds__(256)
rotation_bilinear_v3(const float* __restrict__ theta,
                     const float* __restrict__ image,
                     float* __restrict__ out)
{
    const int b = blockIdx.y;
    const int n = blockIdx.x * 256 + threadIdx.x;  // [0, 6400), exact grid
    const int gy = n / RP_W;                        // mul-shift
    const int gx = n - gy * RP_W;

    const float cx = (RP_W - 1) * 0.5f;
    const float cy = (RP_H - 1) * 0.5f;

    const float th = __ldg(theta + b) * 0.017453292519943295f;
    float s, c;
    __sincosf(th, &s, &c);   // 2x MUFU, ~16cyc each vs ~30-instr slow path

    const float xr = (float)gx - cx;
    const float yr = (float)gy - cy;
    const float sx = fmaf(c, xr, fmaf(s, yr, cx));
    const float sy = fmaf(-s, xr, fmaf(c, yr, cy));

    const int x0 = __float2int_rd(sx);
    const int y0 = __float2int_rd(sy);
    const float fx = sx - (float)x0;
    const float fy = sy - (float)y0;
    const int x1 = x0 + 1;
    const int y1 = y0 + 1;

    const float wx0 = (x0 >= 0 && x0 < RP_W) ? (1.0f - fx) : 0.0f;
    const float wx1 = (x1 >= 0 && x1 < RP_W) ? fx          : 0.0f;
    const float wy0 = (y0 >= 0 && y0 < RP_H) ? (1.0f - fy) : 0.0f;
    const float wy1 = (y1 >= 0 && y1 < RP_H) ? fy          : 0.0f;

    const float w00 = wy0 * wx0;
    const float w01 = wy0 * wx1;
    const float w10 = wy1 * wx0;
    const float w11 = wy1 * wx1;

    const int cx0 = min(max(x0, 0), RP_W - 1);
    const int cx1 = min(max(x1, 0), RP_W - 1);
    const int cy0 = min(max(y0, 0), RP_H - 1);
    const int cy1 = min(max(y1, 0), RP_H - 1);

    const int r0 = cy0 * RP_W;
    const int r1 = cy1 * RP_W;
    const int o00 = r0 + cx0;
    const int o01 = r0 + cx1;
    const int o10 = r1 + cx0;
    const int o11 = r1 + cx1;

    float* op = out + b * (RP_C * RP_N) + n;
    #pragma unroll
    for (int ch = 0; ch < RP_C; ch++) {
        const float* img = image + ch * RP_N;
        float v = w00 * __ldg(img + o00);
        v = fmaf(w01, __ldg(img + o01), v);
        v = fmaf(w10, __ldg(img + o10), v);
        v = fmaf(w11, __ldg(img + o11), v);
        op[ch * RP_N] = v;
    }
}

extern "C" void kernel_launch(void* const* d_in, const int* in_sizes, int n_in,
                              void* d_out, int out_size)
{
    const float* theta = (const float*)d_in[0];  // [4]
    const float* image = (const float*)d_in[1];  // [3,80,80]
    float* out = (float*)d_out;                  // [4,3,80,80]

    dim3 grid(RP_N / 256, RP_B);  // (25, 4) -> 100 blocks x 256 threads, exact
    rotation_bilinear_v3<<<grid, 256>>>(theta, image, out);
}